// round 13
// baseline (speedup 1.0000x reference)
#include <cuda_runtime.h>
#include <cstdint>

#define NPART   100000
#define NFRAMES 500

// Scratch (no allocation allowed): per-frame key records (k0, k1, ks2, pad)
// + pre-shifted integer flip thresholds.
__device__ uint4    g_keys[NFRAMES];
__device__ uint32_t g_thr_shifted[2];   // thresh << 9 ; m<th ⟺ (x0^x1) < (th<<9)

__device__ __forceinline__ uint32_t rotl32(uint32_t x, int r) {
    return __funnelshift_l(x, x, r);  // single SHF
}

// Exact threefry2x32 (setup path).
__device__ __forceinline__ void threefry_plain(uint32_t k0, uint32_t k1,
                                               uint32_t x0, uint32_t x1,
                                               uint32_t &o0, uint32_t &o1) {
    uint32_t ks2 = k0 ^ k1 ^ 0x1BD11BDAu;
    x0 += k0; x1 += k1;
#define RND(r) { x0 += x1; x1 = rotl32(x1, r); x1 ^= x0; }
    RND(13) RND(15) RND(26) RND(6)
    x0 += k1;  x1 += ks2 + 1u;
    RND(17) RND(29) RND(16) RND(24)
    x0 += ks2; x1 += k0 + 2u;
    RND(13) RND(15) RND(26) RND(6)
    x0 += k0;  x1 += k1 + 3u;
    RND(17) RND(29) RND(16) RND(24)
    x0 += k1;  x1 += ks2 + 4u;
    RND(13) RND(15) RND(26) RND(6)
    x0 += ks2; x1 += k0 + 5u;
#undef RND
    o0 = x0; o1 = x1;
}

// ceil-threshold: count of integers m with m * 2^-23 < X (exact pow2 scale).
__device__ __forceinline__ uint32_t thresh_from_prob(float p) {
    float X = p * 8388608.0f;
    uint32_t T = (uint32_t)X;
    if ((float)T < X) T++;
    return T;
}

// jax_threefry_partitionable derivations (verified rel_err = 0).
__global__ void setup_kernel(const int* __restrict__ seed_ptr) {
    int tid = blockIdx.x * blockDim.x + threadIdx.x;
    long long seed = (long long)(*seed_ptr);
    uint32_t k0 = (uint32_t)(((unsigned long long)seed) >> 32);
    uint32_t k1 = (uint32_t)seed;

    uint32_t kp0, kp1, ks0, ks1;
    threefry_plain(k0, k1, 0u, 0u, kp0, kp1);
    threefry_plain(k0, k1, 0u, 1u, ks0, ks1);

    if (tid < NFRAMES) {
        uint32_t o0, o1;
        threefry_plain(ks0, ks1, 0u, (uint32_t)tid, o0, o1);
        g_keys[tid] = make_uint4(o0, o1, o0 ^ o1 ^ 0x1BD11BDAu, 0u);
    }
    if (tid == 0) {
        uint32_t o0, o1;
        threefry_plain(kp0, kp1, 0u, 0u, o0, o1);
        uint32_t bits = o0 ^ o1;
        float u = __uint_as_float((bits >> 9) | 0x3f800000u) - 1.0f;
        float p = u * 0.001f;
        g_thr_shifted[0] = thresh_from_prob(0.2f) << 9;
        g_thr_shifted[1] = thresh_from_prob(p) << 9;
    }
}

// Hot path: R12 champion structure (2 particles/thread, block 128, unroll 2,
// direct __ldg, SEL tail) with injection->round IADD3 fusion: at each interior
// key-injection boundary, x0's injection add is folded into the next round's
// x0 add as one 3-input IADD3 (x1 injected first; semantics identical).
__global__ void __launch_bounds__(128)
hmm_kernel(const float* __restrict__ initial, float4* __restrict__ out) {
    int t = blockIdx.x * blockDim.x + threadIdx.x;
    if (t >= NPART / 2) return;

    const uint32_t t0s = g_thr_shifted[0];
    const uint32_t t1s = g_thr_shifted[1];

    const int na = 2 * t;
    uint32_t sa = (initial[2 * na + 1] > 0.5f) ? 1u : 0u;
    uint32_t sb = (initial[2 * na + 3] > 0.5f) ? 1u : 0u;

    const uint32_t ja_base = 4u * (uint32_t)t;
    const uint32_t jb_base = 4u * (uint32_t)t + 2u;

    float4* optr = out + t;

#pragma unroll 2
    for (int f = 0; f < NFRAMES; f++) {
        const uint4 key = __ldg(&g_keys[f]);          // (k0, k1, ks2, -)
        const uint32_t k0 = key.x, k1 = key.y, ks2 = key.z;

        uint32_t a0 = k0, a1 = (ja_base + sa) + k1;
        uint32_t b0 = k0, b1 = (jb_base + sb) + k1;

        // plain round
#define RND2(r) { a0 += a1; a1 = rotl32(a1, r) ^ a0; \
                  b0 += b1; b1 = rotl32(b1, r) ^ b0; }
        // round with fused x0 injection: x1 += p1+c ; x0 = x0 + p0 + x1 (IADD3)
#define RNDI2(r, p0, p1, c) { a1 += (p1) + (c); a0 += (p0) + a1; a1 = rotl32(a1, r) ^ a0; \
                              b1 += (p1) + (c); b0 += (p0) + b1; b1 = rotl32(b1, r) ^ b0; }
        RND2(13) RND2(15) RND2(26) RND2(6)
        RNDI2(17, k1, ks2, 1u)
        RND2(29) RND2(16) RND2(24)
        RNDI2(13, ks2, k0, 2u)
        RND2(15) RND2(26) RND2(6)
        RNDI2(17, k0, k1, 3u)
        RND2(29) RND2(16) RND2(24)
        RNDI2(13, k1, ks2, 4u)
        RND2(15) RND2(26) RND2(6)
        // final injection (no following round)
        a0 += ks2;  a1 += k0 + 5u;
        b0 += ks2;  b1 += k0 + 5u;
#undef RND2
#undef RNDI2

        // folded compare: (x0^x1) < (th<<9)  ⟺  23-bit draw < th   (exact)
        uint32_t va = a0 ^ a1;
        uint32_t vb = b0 ^ b1;
        sa ^= (va < (sa ? t1s : t0s)) ? 1u : 0u;
        sb ^= (vb < (sb ? t1s : t0s)) ? 1u : 0u;

        *optr = make_float4(sa ? 0.0f : 1.0f, sa ? 1.0f : 0.0f,
                            sb ? 0.0f : 1.0f, sb ? 1.0f : 0.0f);
        optr += NPART / 2;
    }
}

extern "C" void kernel_launch(void* const* d_in, const int* in_sizes, int n_in,
                              void* d_out, int out_size) {
    const float* initial = (const float*)d_in[0];
    const int*   seed    = (const int*)d_in[1];
    float4*      out     = (float4*)d_out;
    (void)in_sizes; (void)n_in; (void)out_size;

    setup_kernel<<<2, 256>>>(seed);
    int threads_needed = NPART / 2;                 // 50000
    int blocks = (threads_needed + 127) / 128;      // 391 blocks of 128
    hmm_kernel<<<blocks, 128>>>(initial, out);
}

// round 14
// speedup vs baseline: 1.0443x; 1.0443x over previous
#include <cuda_runtime.h>
#include <cstdint>

#define NPART   100000
#define NFRAMES 500

__device__ __forceinline__ uint32_t rotl32(uint32_t x, int r) {
    return __funnelshift_l(x, x, r);  // single SHF
}

// Exact threefry2x32 (20 rounds, 5 key injections).
__device__ __forceinline__ void threefry_plain(uint32_t k0, uint32_t k1,
                                               uint32_t x0, uint32_t x1,
                                               uint32_t &o0, uint32_t &o1) {
    uint32_t ks2 = k0 ^ k1 ^ 0x1BD11BDAu;
    x0 += k0; x1 += k1;
#define RND(r) { x0 += x1; x1 = rotl32(x1, r); x1 ^= x0; }
    RND(13) RND(15) RND(26) RND(6)
    x0 += k1;  x1 += ks2 + 1u;
    RND(17) RND(29) RND(16) RND(24)
    x0 += ks2; x1 += k0 + 2u;
    RND(13) RND(15) RND(26) RND(6)
    x0 += k0;  x1 += k1 + 3u;
    RND(17) RND(29) RND(16) RND(24)
    x0 += k1;  x1 += ks2 + 4u;
    RND(13) RND(15) RND(26) RND(6)
    x0 += ks2; x1 += k0 + 5u;
#undef RND
    o0 = x0; o1 = x1;
}

// ceil-threshold: count of integers m with m * 2^-23 < X (exact pow2 scale).
__device__ __forceinline__ uint32_t thresh_from_prob(float p) {
    float X = p * 8388608.0f;
    uint32_t T = (uint32_t)X;
    if ((float)T < X) T++;
    return T;
}

// Single fused kernel: per-block key derivation (jax_threefry_partitionable,
// verified rel_err = 0) into shared memory, then the R12-champion hot loop.
__global__ void __launch_bounds__(128)
hmm_kernel(const float* __restrict__ initial, const int* __restrict__ seed_ptr,
           float4* __restrict__ out) {
    __shared__ uint4    skeys[NFRAMES];     // (k0, k1, ks2, -)
    __shared__ uint32_t sthr[2];            // thresh << 9

    // ---- prologue: every block derives all frame keys (cheap, parallel) ----
    {
        long long seed = (long long)(*seed_ptr);
        uint32_t k0 = (uint32_t)(((unsigned long long)seed) >> 32);
        uint32_t k1 = (uint32_t)seed;

        // split(key,2) foldlike: kp = tf(key,0,0), ks = tf(key,0,1)
        uint32_t kp0, kp1, ks0, ks1;
        threefry_plain(k0, k1, 0u, 0u, kp0, kp1);
        threefry_plain(k0, k1, 0u, 1u, ks0, ks1);

        // split(ks, 500) foldlike: keys[f] = tf(ks, 0, f)
        for (int i = threadIdx.x; i < NFRAMES; i += 128) {
            uint32_t o0, o1;
            threefry_plain(ks0, ks1, 0u, (uint32_t)i, o0, o1);
            skeys[i] = make_uint4(o0, o1, o0 ^ o1 ^ 0x1BD11BDAu, 0u);
        }
        if (threadIdx.x == 0) {
            // p = uniform(kp, ()) * 0.001 ; bits = o0 ^ o1 under kp
            uint32_t o0, o1;
            threefry_plain(kp0, kp1, 0u, 0u, o0, o1);
            uint32_t bits = o0 ^ o1;
            float u = __uint_as_float((bits >> 9) | 0x3f800000u) - 1.0f;
            float p = u * 0.001f;
            sthr[0] = thresh_from_prob(0.2f) << 9;
            sthr[1] = thresh_from_prob(p) << 9;
        }
    }
    __syncthreads();

    int t = blockIdx.x * blockDim.x + threadIdx.x;
    if (t < NPART / 2) {
        const uint32_t t0s = sthr[0];
        const uint32_t t1s = sthr[1];

        const int na = 2 * t;
        uint32_t sa = (initial[2 * na + 1] > 0.5f) ? 1u : 0u;
        uint32_t sb = (initial[2 * na + 3] > 0.5f) ? 1u : 0u;

        const uint32_t ja_base = 4u * (uint32_t)t;
        const uint32_t jb_base = 4u * (uint32_t)t + 2u;

        float4* optr = out + t;

#pragma unroll 2
        for (int f = 0; f < NFRAMES; f++) {
            const uint4 key = skeys[f];               // LDS, uniform broadcast
            const uint32_t k0 = key.x, k1 = key.y, ks2 = key.z;

            uint32_t a0 = k0, a1 = (ja_base + sa) + k1;
            uint32_t b0 = k0, b1 = (jb_base + sb) + k1;

#define RND2(r) { a0 += a1; a1 = rotl32(a1, r) ^ a0; \
                  b0 += b1; b1 = rotl32(b1, r) ^ b0; }
#define INJ2(p0, p1, c) { a0 += (p0); a1 += (p1) + (c); \
                          b0 += (p0); b1 += (p1) + (c); }
            RND2(13) RND2(15) RND2(26) RND2(6)
            INJ2(k1, ks2, 1u)
            RND2(17) RND2(29) RND2(16) RND2(24)
            INJ2(ks2, k0, 2u)
            RND2(13) RND2(15) RND2(26) RND2(6)
            INJ2(k0, k1, 3u)
            RND2(17) RND2(29) RND2(16) RND2(24)
            INJ2(k1, ks2, 4u)
            RND2(13) RND2(15) RND2(26) RND2(6)
            INJ2(ks2, k0, 5u)
#undef RND2
#undef INJ2

            // folded compare: (x0^x1) < (th<<9)  ⟺  23-bit draw < th (exact)
            uint32_t va = a0 ^ a1;
            uint32_t vb = b0 ^ b1;
            sa ^= (va < (sa ? t1s : t0s)) ? 1u : 0u;
            sb ^= (vb < (sb ? t1s : t0s)) ? 1u : 0u;

            *optr = make_float4(sa ? 0.0f : 1.0f, sa ? 1.0f : 0.0f,
                                sb ? 0.0f : 1.0f, sb ? 1.0f : 0.0f);
            optr += NPART / 2;
        }
    }
}

extern "C" void kernel_launch(void* const* d_in, const int* in_sizes, int n_in,
                              void* d_out, int out_size) {
    const float* initial = (const float*)d_in[0];
    const int*   seed    = (const int*)d_in[1];
    float4*      out     = (float4*)d_out;
    (void)in_sizes; (void)n_in; (void)out_size;

    int threads_needed = NPART / 2;                 // 50000
    int blocks = (threads_needed + 127) / 128;      // 391 blocks of 128
    hmm_kernel<<<blocks, 128>>>(initial, seed, out);
}